// round 1
// baseline (speedup 1.0000x reference)
#include <cuda_runtime.h>
#include <math.h>

#define TT   512
#define HH   64
#define DD   576
#define DV   512
#define TOPK 1024
#define TILE 32
#define NTILES (TOPK / TILE)   // 32
#define HG   16                // heads per block
#define NHG  (HH / HG)         // 4
#define KV_STRIDE 577          // odd stride -> conflict-free banks

// dynamic smem layout (floats):
//   sKV  [32*577]
//   sS   [16*33]
//   sP   [16*33]
//   sC   [16]
//   sM   [16]
//   sL   [16]
//   sIdx [32] (int)
#define SMEM_FLOATS (TILE*KV_STRIDE + 2*HG*33 + 3*HG)
#define SMEM_BYTES  (SMEM_FLOATS*4 + TILE*4)

__global__ void __launch_bounds__(256, 1)
mla_sparse_attn_kernel(const float* __restrict__ q,     // [T,H,D]
                       const float* __restrict__ kv,    // [NKV,D]
                       const int*   __restrict__ topk,  // [T,TOPK]
                       const float* __restrict__ sink,  // [H]
                       float*       __restrict__ out)   // [T,H,DV]
{
    extern __shared__ float smem[];
    float* sKV = smem;                       // [32][577]
    float* sS  = sKV + TILE * KV_STRIDE;     // [16][33]
    float* sP  = sS + HG * 33;               // [16][33]
    float* sC  = sP + HG * 33;               // [16]
    float* sM  = sC + HG;                    // [16]
    float* sL  = sM + HG;                    // [16]
    int*   sIdx = (int*)(sL + HG);           // [32]

    const int hg   = blockIdx.x;             // 0..3
    const int t    = blockIdx.y;             // 0..511
    const int tid  = threadIdx.x;
    const int lane = tid & 31;
    const int w    = tid >> 5;               // warp 0..7

    const float scale = 1.0f / 24.0f;        // 1/sqrt(576)

    if (tid < HG) { sM[tid] = -INFINITY; sL[tid] = 0.0f; }

    // ---- score-phase assignment: warp covers 4 heads x 16 kv-rows ----
    const int s_hbase = (w & 3) * 4;         // local head base (0,4,8,12)
    const int s_kbase = (w >> 2) * 16;       // kv half (0 or 16)

    // q for 4 heads in registers, element d = lane + 32*i
    float qreg[4][18];
    #pragma unroll
    for (int j = 0; j < 4; ++j) {
        const float* qp = q + ((size_t)t * HH + (size_t)hg * HG + s_hbase + j) * DD + lane;
        #pragma unroll
        for (int i = 0; i < 18; ++i) qreg[j][i] = qp[i * 32];
    }

    // ---- PV-phase assignment: warp covers 2 heads, lane owns v-dims lane+32*i ----
    const int p_h0 = w * 2;                  // local heads p_h0, p_h0+1
    float acc0[16], acc1[16];
    #pragma unroll
    for (int i = 0; i < 16; ++i) { acc0[i] = 0.0f; acc1[i] = 0.0f; }

    const int* tkp = topk + (size_t)t * TOPK;

    for (int kt = 0; kt < NTILES; ++kt) {
        // 1) load tile indices
        if (tid < TILE) sIdx[tid] = tkp[kt * TILE + tid];
        __syncthreads();   // also guarantees previous PV finished reading sKV

        // 2) gather: lane = row, warp = 72-float segment (contiguous 288B per thread)
        {
            int idxv = sIdx[lane];
            int row  = idxv < 0 ? 0 : idxv;
            const float4* src = (const float4*)(kv + (size_t)row * DD) + w * 18;
            float* dst = sKV + lane * KV_STRIDE + w * 72;
            #pragma unroll
            for (int i = 0; i < 18; ++i) {
                float4 v = src[i];
                dst[i * 4 + 0] = v.x;
                dst[i * 4 + 1] = v.y;
                dst[i * 4 + 2] = v.z;
                dst[i * 4 + 3] = v.w;
            }
        }
        __syncthreads();

        // 3) scores: 4 heads x 16 k per warp, butterfly reduce over lanes
        #pragma unroll 1
        for (int kk = 0; kk < 16; ++kk) {
            const int k = s_kbase + kk;
            const float* kvp = sKV + k * KV_STRIDE + lane;
            float s0 = 0.f, s1 = 0.f, s2 = 0.f, s3 = 0.f;
            #pragma unroll
            for (int i = 0; i < 18; ++i) {
                float v = kvp[i * 32];
                s0 += qreg[0][i] * v;
                s1 += qreg[1][i] * v;
                s2 += qreg[2][i] * v;
                s3 += qreg[3][i] * v;
            }
            #pragma unroll
            for (int off = 16; off; off >>= 1) {
                s0 += __shfl_xor_sync(0xFFFFFFFFu, s0, off);
                s1 += __shfl_xor_sync(0xFFFFFFFFu, s1, off);
                s2 += __shfl_xor_sync(0xFFFFFFFFu, s2, off);
                s3 += __shfl_xor_sync(0xFFFFFFFFu, s3, off);
            }
            if (lane == 0) {
                bool valid = sIdx[k] >= 0;
                sS[(s_hbase + 0) * 33 + k] = valid ? s0 * scale : -INFINITY;
                sS[(s_hbase + 1) * 33 + k] = valid ? s1 * scale : -INFINITY;
                sS[(s_hbase + 2) * 33 + k] = valid ? s2 * scale : -INFINITY;
                sS[(s_hbase + 3) * 33 + k] = valid ? s3 * scale : -INFINITY;
            }
        }
        __syncthreads();

        // 4) online softmax (one thread per head)
        if (tid < HG) {
            const int h = tid;
            float m_old = sM[h];
            float tmax = -INFINITY;
            #pragma unroll
            for (int k = 0; k < TILE; ++k) tmax = fmaxf(tmax, sS[h * 33 + k]);
            float m_new = fmaxf(m_old, tmax);
            float c, l = sL[h];
            if (m_new == -INFINITY) {
                c = 1.0f;
                #pragma unroll
                for (int k = 0; k < TILE; ++k) sP[h * 33 + k] = 0.0f;
            } else {
                c = __expf(m_old - m_new);   // exp(-inf) = 0 on first tile
                float ls = 0.0f;
                #pragma unroll
                for (int k = 0; k < TILE; ++k) {
                    float p = __expf(sS[h * 33 + k] - m_new);
                    sP[h * 33 + k] = p;
                    ls += p;
                }
                l = l * c + ls;
            }
            sC[h] = c; sM[h] = m_new; sL[h] = l;
        }
        __syncthreads();

        // 5) PV rank-32 update: warp handles 2 heads, lane owns d = lane+32*i
        {
            float c0 = sC[p_h0], c1 = sC[p_h0 + 1];
            #pragma unroll
            for (int i = 0; i < 16; ++i) { acc0[i] *= c0; acc1[i] *= c1; }
            #pragma unroll 1
            for (int k = 0; k < TILE; ++k) {
                float p0 = sP[p_h0 * 33 + k];
                float p1 = sP[(p_h0 + 1) * 33 + k];
                const float* vp = sKV + k * KV_STRIDE + lane;
                #pragma unroll
                for (int i = 0; i < 16; ++i) {
                    float v = vp[i * 32];
                    acc0[i] += p0 * v;
                    acc1[i] += p1 * v;
                }
            }
        }
        // next-iteration top-of-loop barrier protects sKV before regather
    }

    // epilogue: fold in the sink logit exactly as the reference does
    {
        const int hglob0 = hg * HG + p_h0;
        const int hglob1 = hglob0 + 1;

        float m0 = sM[p_h0],     l0 = sL[p_h0],     sk0 = sink[hglob0];
        float m1 = sM[p_h0 + 1], l1 = sL[p_h0 + 1], sk1 = sink[hglob1];

        float mf0 = fmaxf(m0, sk0);
        float f0  = __expf(m0 - mf0);
        float den0 = l0 * f0 + __expf(sk0 - mf0);
        float r0  = f0 / den0;

        float mf1 = fmaxf(m1, sk1);
        float f1  = __expf(m1 - mf1);
        float den1 = l1 * f1 + __expf(sk1 - mf1);
        float r1  = f1 / den1;

        float* op0 = out + ((size_t)t * HH + hglob0) * DV + lane;
        float* op1 = out + ((size_t)t * HH + hglob1) * DV + lane;
        #pragma unroll
        for (int i = 0; i < 16; ++i) {
            op0[i * 32] = acc0[i] * r0;
            op1[i * 32] = acc1[i] * r1;
        }
    }
}

extern "C" void kernel_launch(void* const* d_in, const int* in_sizes, int n_in,
                              void* d_out, int out_size)
{
    const float* q    = (const float*)d_in[0];
    const float* kv   = (const float*)d_in[1];
    const int*   topk = (const int*)d_in[2];
    const float* sink = (const float*)d_in[3];
    float*       out  = (float*)d_out;

    cudaFuncSetAttribute(mla_sparse_attn_kernel,
                         cudaFuncAttributeMaxDynamicSharedMemorySize, SMEM_BYTES);

    dim3 grid(NHG, TT);
    dim3 block(256);
    mla_sparse_attn_kernel<<<grid, block, SMEM_BYTES>>>(q, kv, topk, sink, out);
}